// round 1
// baseline (speedup 1.0000x reference)
#include <cuda_runtime.h>
#include <math.h>

#define BATCH  4
#define CDIM   192
#define NHEADS 8
#define HDIM   24
#define HWN    65536
#define OC3    576   // 3*CDIM

// ---- scratch (device globals; no allocation allowed) ----
__device__ float g_qkv [(size_t)BATCH * OC3 * HWN];   // qkv after 1x1 conv (604MB)
__device__ float g_conv[(size_t)BATCH * OC3 * HWN];   // after depthwise 3x3 (604MB)
__device__ float g_gram[BATCH * NHEADS * 624];        // per (b,h): 576 gram + 24 |q|^2 + 24 |k|^2
__device__ float g_M   [BATCH * CDIM * CDIM];         // fused proj @ attn matrices

// ============================================================
// K1/K5: C[b][m][n] = sum_k A[b][m][k] * B[b][k][n], N = 65536
// BM=64, BN=128, BK=16, 256 threads, 8x4 per-thread microtile.
// ============================================================
__global__ __launch_bounds__(256) void gemm_kernel(
    const float* __restrict__ A, size_t aStride,
    const float* __restrict__ Bm, size_t bStride,
    float* __restrict__ Cm, size_t cStride, int K)
{
    __shared__ alignas(16) float As[16][68];   // padded, transposed [k][m]
    __shared__ alignas(16) float Bs[16][128];

    int bz = blockIdx.z;
    const float* Ab = A  + (size_t)bz * aStride;
    const float* Bb = Bm + (size_t)bz * bStride;
    float*       Cb = Cm + (size_t)bz * cStride;

    int m0 = blockIdx.y * 64;
    int n0 = blockIdx.x * 128;
    int tid = threadIdx.x;
    int tm0 = (tid >> 5) * 8;    // warp id -> m offset (a-broadcast within warp)
    int tn0 = (tid & 31) * 4;
    int am  = tid >> 2;          // A tile: 64 rows x 16 k, float4 per thread
    int ak  = (tid & 3) * 4;
    int br  = tid >> 5;          // B tile: rows br and br+8
    int bc  = (tid & 31) * 4;

    float acc[8][4];
#pragma unroll
    for (int i = 0; i < 8; i++)
#pragma unroll
        for (int j = 0; j < 4; j++) acc[i][j] = 0.f;

    for (int k0 = 0; k0 < K; k0 += 16) {
        float4 av = *(const float4*)&Ab[(size_t)(m0 + am) * K + k0 + ak];
        float4 b0 = *(const float4*)&Bb[(size_t)(k0 + br) * HWN + n0 + bc];
        float4 b1 = *(const float4*)&Bb[(size_t)(k0 + br + 8) * HWN + n0 + bc];
        __syncthreads();
        As[ak + 0][am] = av.x; As[ak + 1][am] = av.y;
        As[ak + 2][am] = av.z; As[ak + 3][am] = av.w;
        *(float4*)&Bs[br][bc]     = b0;
        *(float4*)&Bs[br + 8][bc] = b1;
        __syncthreads();
#pragma unroll
        for (int k = 0; k < 16; k++) {
            float4 a0 = *(const float4*)&As[k][tm0];
            float4 a1 = *(const float4*)&As[k][tm0 + 4];
            float4 bb = *(const float4*)&Bs[k][tn0];
            float a[8] = {a0.x, a0.y, a0.z, a0.w, a1.x, a1.y, a1.z, a1.w};
            float bv[4] = {bb.x, bb.y, bb.z, bb.w};
#pragma unroll
            for (int i = 0; i < 8; i++)
#pragma unroll
                for (int j = 0; j < 4; j++)
                    acc[i][j] += a[i] * bv[j];
        }
    }
#pragma unroll
    for (int i = 0; i < 8; i++) {
        float4 o = {acc[i][0], acc[i][1], acc[i][2], acc[i][3]};
        *(float4*)&Cb[(size_t)(m0 + tm0 + i) * HWN + n0 + tn0] = o;
    }
}

// ============================================================
// K2: depthwise 3x3, pad=1. Each thread: 4 consecutive x pixels.
// ============================================================
__global__ __launch_bounds__(256) void dwconv_kernel(
    const float* __restrict__ in, const float* __restrict__ wAll,
    float* __restrict__ out)
{
    int idx = blockIdx.x * 256 + threadIdx.x;     // over BATCH*OC3*HWN/4
    int p4 = idx & 16383;                         // pixel-group within channel
    int bc = idx >> 14;                           // b*576 + ch
    int ch = bc % OC3;
    int y  = p4 >> 6;
    int x0 = (p4 & 63) << 2;
    const float* base = in + (size_t)bc * HWN;

    float w[9];
#pragma unroll
    for (int i = 0; i < 9; i++) w[i] = __ldg(&wAll[ch * 9 + i]);

    float s0 = 0.f, s1 = 0.f, s2 = 0.f, s3 = 0.f;
#pragma unroll
    for (int ky = 0; ky < 3; ky++) {
        int yy = y + ky - 1;
        if ((unsigned)yy >= 256u) continue;
        const float* row = base + yy * 256;
        float4 v    = *(const float4*)&row[x0];
        float left  = (x0 > 0)   ? row[x0 - 1] : 0.f;
        float right = (x0 < 252) ? row[x0 + 4] : 0.f;
        float w0 = w[ky * 3], w1 = w[ky * 3 + 1], w2 = w[ky * 3 + 2];
        s0 += left * w0 + v.x  * w1 + v.y  * w2;
        s1 += v.x  * w0 + v.y  * w1 + v.z  * w2;
        s2 += v.y  * w0 + v.z  * w1 + v.w  * w2;
        s3 += v.z  * w0 + v.w  * w1 + right * w2;
    }
    float4 o = {s0, s1, s2, s3};
    *(float4*)&out[(size_t)idx * 4] = o;
}

// ============================================================
// zero the gram accumulators (atomics target)
// ============================================================
__global__ void zero_gram() {
    int i = blockIdx.x * blockDim.x + threadIdx.x;
    if (i < BATCH * NHEADS * 624) g_gram[i] = 0.f;
}

// ============================================================
// K3: per (b,h): G[d][e] = sum_n q[d,n]*k[e,n]; plus |q_d|^2, |k_e|^2.
// 576 threads (one per (d,e)), smem-tiled over n, atomicAdd partials.
// ============================================================
#define GPAD 129
__global__ __launch_bounds__(576) void gram_kernel(
    const float* __restrict__ conv, int nPer)
{
    __shared__ float qs[24 * GPAD];
    __shared__ float ks[24 * GPAD];
    int bh = blockIdx.y;
    int b = bh >> 3, hh = bh & 7;
    const float* qb = conv + ((size_t)b * OC3 + hh * HDIM) * HWN;
    const float* kb = conv + ((size_t)b * OC3 + CDIM + hh * HDIM) * HWN;
    int t = threadIdx.x;            // 0..575
    int d = t / 24, e = t - d * 24;

    float accQK = 0.f, acc2 = 0.f;
    int nStart = blockIdx.x * nPer;
    for (int n0 = nStart; n0 < nStart + nPer; n0 += 128) {
        __syncthreads();
        for (int i = t; i < 24 * 128; i += 576) {
            int r = i >> 7, c = i & 127;
            qs[r * GPAD + c] = qb[(size_t)r * HWN + n0 + c];
            ks[r * GPAD + c] = kb[(size_t)r * HWN + n0 + c];
        }
        __syncthreads();
        const float* qrow = &qs[d * GPAD];
        const float* krow = &ks[e * GPAD];
#pragma unroll 8
        for (int n = 0; n < 128; n++) accQK += qrow[n] * krow[n];
        if (t < 48) {
            const float* srow = (t < 24) ? &qs[t * GPAD] : &ks[(t - 24) * GPAD];
#pragma unroll 8
            for (int n = 0; n < 128; n++) acc2 += srow[n] * srow[n];
        }
    }
    float* gb = &g_gram[bh * 624];
    atomicAdd(&gb[d * 24 + e], accQK);
    if (t < 48) atomicAdd(&gb[576 + t], acc2);
}

// ============================================================
// K4: normalize gram -> softmax -> fuse with proj: M_b = proj @ blockdiag(attn)
// ============================================================
__global__ __launch_bounds__(256) void attn_proj_kernel(
    const float* __restrict__ projw, const float* __restrict__ temp)
{
    __shared__ float attn_s[NHEADS * HDIM * HDIM];   // [h][d][e]
    int b = blockIdx.x;
    int t = threadIdx.x;
    if (t < CDIM) {
        int hh = t / HDIM, d = t % HDIM;
        const float* G = &g_gram[(b * NHEADS + hh) * 624];
        float nq = fmaxf(sqrtf(G[576 + d]), 1e-12f);
        float tm = temp[hh];
        float row[HDIM];
        float mx = -1e30f;
#pragma unroll
        for (int e = 0; e < HDIM; e++) {
            float nk = fmaxf(sqrtf(G[600 + e]), 1e-12f);
            float a = G[d * 24 + e] / (nq * nk) * tm;
            row[e] = a; mx = fmaxf(mx, a);
        }
        float s = 0.f;
#pragma unroll
        for (int e = 0; e < HDIM; e++) { row[e] = expf(row[e] - mx); s += row[e]; }
        float inv = 1.f / s;
#pragma unroll
        for (int e = 0; e < HDIM; e++) attn_s[hh * 576 + d * 24 + e] = row[e] * inv;
    }
    __syncthreads();
    if (t < CDIM) {
        int o = t;
        const float* pr = &projw[o * CDIM];
        for (int hh = 0; hh < NHEADS; hh++) {
#pragma unroll
            for (int e = 0; e < HDIM; e++) {
                float acc = 0.f;
#pragma unroll
                for (int d = 0; d < HDIM; d++)
                    acc += pr[hh * 24 + d] * attn_s[hh * 576 + d * 24 + e];
                g_M[((size_t)b * CDIM + o) * CDIM + hh * 24 + e] = acc;
            }
        }
    }
}

// ============================================================
extern "C" void kernel_launch(void* const* d_in, const int* in_sizes, int n_in,
                              void* d_out, int out_size)
{
    const float* x      = (const float*)d_in[0];  // [4,192,256,256]
    const float* qkv_w  = (const float*)d_in[1];  // [576,192]
    const float* dw_w   = (const float*)d_in[2];  // [576,1,3,3]
    const float* proj_w = (const float*)d_in[3];  // [192,192]
    const float* temp   = (const float*)d_in[4];  // [8,1,1]
    float* out = (float*)d_out;                   // [4,192,256,256]

    float *qkv, *convp, *Mp;
    cudaGetSymbolAddress((void**)&qkv,   g_qkv);
    cudaGetSymbolAddress((void**)&convp, g_conv);
    cudaGetSymbolAddress((void**)&Mp,    g_M);

    // K1: qkv = W_qkv @ x   (A shared across batch => stride 0)
    dim3 g1(HWN / 128, OC3 / 64, BATCH);
    gemm_kernel<<<g1, 256>>>(qkv_w, 0,
                             x, (size_t)CDIM * HWN,
                             qkv, (size_t)OC3 * HWN, CDIM);

    // K2: depthwise 3x3
    dwconv_kernel<<<(BATCH * OC3 * HWN / 4) / 256, 256>>>(qkv, dw_w, convp);

    // K3 prep + gram reduction
    zero_gram<<<(BATCH * NHEADS * 624 + 255) / 256, 256>>>();
    dim3 g3(16, BATCH * NHEADS);
    gram_kernel<<<g3, 576>>>(convp, HWN / 16);

    // K4: softmax + fold proj into per-batch 192x192 matrix
    attn_proj_kernel<<<BATCH, 256>>>(proj_w, temp);

    // K5: out = M_b @ v   (v = conv channels [384..576))
    dim3 g5(HWN / 128, CDIM / 64, BATCH);
    gemm_kernel<<<g5, 256>>>(Mp, (size_t)CDIM * CDIM,
                             convp + (size_t)2 * CDIM * HWN, (size_t)OC3 * HWN,
                             out, (size_t)CDIM * HWN, CDIM);
}